// round 2
// baseline (speedup 1.0000x reference)
#include <cuda_runtime.h>
#include <cstdint>

#define B_    64
#define N_    2048
#define J_    32
#define D_    16
#define E_    16
#define JD_   512
#define EPS_  1e-8f
#define ICH   74            // i-chunks; i = ic + k*74
#define XROW  452           // 28*16 + 4 pad (bank-conflict-free LDS.128)

// Scratch (device globals: allocation-free rule)
__device__ float g_part[(size_t)ICH * JD_ * B_];   // [ic][jd][b] partial s
__device__ float g_v[2][B_ * JD_];                 // v1, (v1+v2)

__device__ __forceinline__ uint32_t smem_u32(const void* p) {
    return (uint32_t)__cvta_generic_to_shared(p);
}
__device__ __forceinline__ void cp16(uint32_t d, const float* s) {
    asm volatile("cp.async.cg.shared.global [%0], [%1], 16;" :: "r"(d), "l"(s));
}
__device__ __forceinline__ void cp_commit() {
    asm volatile("cp.async.commit_group;");
}
__device__ __forceinline__ void cp_wait0() {
    asm volatile("cp.async.wait_group 0;");
}

// ---------------------------------------------------------------------------
// Routing pass with on-the-fly recomputation of u.
// Grid (ICH, 2): CTA = (i-chunk ic, b-half bh). 512 threads = 16 warps.
// warp w owns j = {w, w+16}; lane = local b (0..31).
// For each i in the chunk:
//   stage W[i] (32KB) in smem (double-buffered cp.async)
//   u[j,d] = sum_e W[i,j,d,e] * x[b,i,e]   (W via broadcast LDS.128)
//   vIdx>=0: logit[j] = u.v[b,j,:], cross-warp softmax over j via smem
//   vIdx<0 : c = 1/32 (iteration 1)
//   acc[j,d] += c[j]*u[j,d]
// Partials written to g_part[ic][jd][b] (coalesced), reduced in squash.
// ---------------------------------------------------------------------------
__global__ __launch_bounds__(512, 1) void k_pass(int vIdx,
        const float* __restrict__ x, const float* __restrict__ w) {
    extern __shared__ float sm[];
    float* ws  = sm;                       // [2][8192]  W double buffer
    float* xs  = sm + 16384;               // [32][XROW] x tile
    float* sml = xs + 32 * XROW;           // [32][33]   logits
    float* smc = sml + 32 * 33;            // [32][33]   c

    const int ic   = blockIdx.x;
    const int bh   = blockIdx.y;
    const int t    = threadIdx.x;
    const int wid  = t >> 5;               // 0..15
    const int lane = t & 31;               // local b
    const int bg   = bh * 32 + lane;       // global b
    const int nI   = (ic < 50) ? 28 : 27;  // 2048 = 74*27 + 50

    // preload x for all i's of this chunk
    const int xtot = 32 * nI * 16;
    for (int idx = t; idx < xtot; idx += 512) {
        int b = idx / (nI * 16);
        int r = idx - b * nI * 16;
        int k = r >> 4, e = r & 15;
        xs[b * XROW + k * 16 + e] =
            x[((size_t)(bh * 32 + b) * N_ + ic + k * ICH) * 16 + e];
    }

    // preload W for k=0
    {
        const float* wp = w + (size_t)ic * 8192;
        uint32_t dd = smem_u32(ws) + t * 64;
        cp16(dd,      wp + t * 16);
        cp16(dd + 16, wp + t * 16 + 4);
        cp16(dd + 32, wp + t * 16 + 8);
        cp16(dd + 48, wp + t * 16 + 12);
        cp_commit();
    }
    cp_wait0();
    __syncthreads();

    float acc[2][16];
#pragma unroll
    for (int jj = 0; jj < 2; jj++)
#pragma unroll
        for (int d = 0; d < 16; d++) acc[jj][d] = 0.f;

    for (int k = 0; k < nI; k++) {
        const float* wcur = ws + (k & 1) * 8192;

        // prefetch next W tile
        if (k + 1 < nI) {
            const float* wp = w + (size_t)(ic + (k + 1) * ICH) * 8192;
            uint32_t dd = smem_u32(ws + ((k + 1) & 1) * 8192) + t * 64;
            cp16(dd,      wp + t * 16);
            cp16(dd + 16, wp + t * 16 + 4);
            cp16(dd + 32, wp + t * 16 + 8);
            cp16(dd + 48, wp + t * 16 + 12);
            cp_commit();
        }

        // x in registers (conflict-free LDS.128: row stride 452)
        const float4* xp = (const float4*)(xs + lane * XROW + k * 16);
        const float4 x0 = xp[0], x1 = xp[1], x2 = xp[2], x3 = xp[3];

        float u[2][16];
        float lg[2];
#pragma unroll
        for (int jj = 0; jj < 2; jj++) {
            const int j = wid + jj * 16;
            const float4* wr = (const float4*)(wcur + j * 256);
#pragma unroll
            for (int d = 0; d < 16; d++) {
                float4 a = wr[d * 4 + 0];      // broadcast LDS.128
                float4 b4 = wr[d * 4 + 1];
                float4 c4 = wr[d * 4 + 2];
                float4 d4 = wr[d * 4 + 3];
                u[jj][d] = a.x*x0.x + a.y*x0.y + a.z*x0.z + a.w*x0.w
                         + b4.x*x1.x + b4.y*x1.y + b4.z*x1.z + b4.w*x1.w
                         + c4.x*x2.x + c4.y*x2.y + c4.z*x2.z + c4.w*x2.w
                         + d4.x*x3.x + d4.y*x3.y + d4.z*x3.z + d4.w*x3.w;
            }
            if (vIdx >= 0) {
                const float4* vp = (const float4*)(&g_v[vIdx][(size_t)bg * JD_ + j * 16]);
                float4 v0 = vp[0], v1 = vp[1], v2 = vp[2], v3 = vp[3];
                lg[jj] = u[jj][0]*v0.x + u[jj][1]*v0.y + u[jj][2]*v0.z + u[jj][3]*v0.w
                       + u[jj][4]*v1.x + u[jj][5]*v1.y + u[jj][6]*v1.z + u[jj][7]*v1.w
                       + u[jj][8]*v2.x + u[jj][9]*v2.y + u[jj][10]*v2.z + u[jj][11]*v2.w
                       + u[jj][12]*v3.x + u[jj][13]*v3.y + u[jj][14]*v3.z + u[jj][15]*v3.w;
            }
        }

        float c0, c1;
        if (vIdx >= 0) {
            sml[lane * 33 + wid]      = lg[0];
            sml[lane * 33 + wid + 16] = lg[1];
            __syncthreads();
            // reduce phase: warp 'wid' handles b = wid and wid+16; lane = j
#pragma unroll
            for (int bb2 = 0; bb2 < 2; bb2++) {
                const int bb = wid + bb2 * 16;
                float l = sml[bb * 33 + lane];
                float m = l;
#pragma unroll
                for (int o = 16; o > 0; o >>= 1)
                    m = fmaxf(m, __shfl_xor_sync(0xffffffffu, m, o));
                float ex = __expf(l - m);
                float ssum = ex;
#pragma unroll
                for (int o = 16; o > 0; o >>= 1)
                    ssum += __shfl_xor_sync(0xffffffffu, ssum, o);
                smc[bb * 33 + lane] = ex / ssum;
            }
            __syncthreads();
            c0 = smc[lane * 33 + wid];
            c1 = smc[lane * 33 + wid + 16];
        } else {
            c0 = c1 = 1.0f / 32.0f;
        }

#pragma unroll
        for (int d = 0; d < 16; d++) {
            acc[0][d] += c0 * u[0][d];
            acc[1][d] += c1 * u[1][d];
        }

        cp_wait0();
        __syncthreads();   // protects W buffer swap + sml/smc reuse
    }

    // write partials: g_part[ic][j*16+d][b]  (lanes = b -> coalesced)
#pragma unroll
    for (int jj = 0; jj < 2; jj++) {
        const int j = wid + jj * 16;
#pragma unroll
        for (int d = 0; d < 16; d++)
            g_part[((size_t)ic * JD_ + j * 16 + d) * B_ + bg] = acc[jj][d];
    }
}

// ---------------------------------------------------------------------------
// Reduce partials over ic, squash over capsule axis J (per (b,d)).
// mode 0: g_v[0] = squash(s)              (v1)
// mode 1: g_v[1] = squash(s) + g_v[0]     (v1 + v2, additive logits)
// ---------------------------------------------------------------------------
__global__ void k_squash2(int mode) {
    const int b = blockIdx.x;
    const int t = threadIdx.x;               // t = j*16 + d
    float s = 0.f;
#pragma unroll 4
    for (int ic = 0; ic < ICH; ic++)
        s += g_part[((size_t)ic * JD_ + t) * B_ + b];

    __shared__ float sq[16];
    if (t < 16) sq[t] = 0.f;
    __syncthreads();
    atomicAdd(&sq[t & 15], s * s);
    __syncthreads();
    float q = sq[t & 15];
    float v = s * (q / (1.f + q)) * rsqrtf(q + EPS_);
    if (mode == 0) g_v[0][b * JD_ + t] = v;
    else           g_v[1][b * JD_ + t] = v + g_v[0][b * JD_ + t];
}

// ---------------------------------------------------------------------------
// Reduce partials over ic, final squash over D (per (b,j)).
// ---------------------------------------------------------------------------
__global__ void k_final2(float* __restrict__ out) {
    const int b = blockIdx.x;
    const int t = threadIdx.x;               // t = j*16 + d
    float s = 0.f;
#pragma unroll 4
    for (int ic = 0; ic < ICH; ic++)
        s += g_part[((size_t)ic * JD_ + t) * B_ + b];

    float q = s * s;
#pragma unroll
    for (int o = 1; o < 16; o <<= 1)         // groups of 16 lanes = same j
        q += __shfl_xor_sync(0xffffffffu, q, o);
    float v = s * (q / (1.f + q)) * rsqrtf(q + EPS_);
    out[b * JD_ + t] = v;
}

// ---------------------------------------------------------------------------
extern "C" void kernel_launch(void* const* d_in, const int* in_sizes, int n_in,
                              void* d_out, int out_size) {
    const float* x = (const float*)d_in[0];
    const float* w = (const float*)d_in[1];
    if (in_sizes[0] != B_ * N_ * E_) {       // defensive input-order check
        x = (const float*)d_in[1];
        w = (const float*)d_in[0];
    }

    const int smemB = (16384 + 32 * XROW + 2 * 32 * 33) * 4;   // ~128.8 KB
    cudaFuncSetAttribute(k_pass, cudaFuncAttributeMaxDynamicSharedMemorySize, smemB);

    dim3 g(ICH, 2);
    k_pass<<<g, 512, smemB>>>(-1, x, w);     // iter 1: uniform c -> s1
    k_squash2<<<B_, JD_>>>(0);               // v1 = squash_J(s1)
    k_pass<<<g, 512, smemB>>>(0, x, w);      // iter 2: c = softmax(u.v1) -> s2
    k_squash2<<<B_, JD_>>>(1);               // vsum = squash_J(s2) + v1
    k_pass<<<g, 512, smemB>>>(1, x, w);      // final: c = softmax(u.vsum) -> s3
    k_final2<<<B_, JD_>>>((float*)d_out);    // out = squash_D(s3)
}

// round 3
// speedup vs baseline: 2.4659x; 2.4659x over previous
#include <cuda_runtime.h>
#include <cuda_fp16.h>
#include <cstdint>

#define B_    64
#define N_    2048
#define JD_   512
#define EPS_  1e-8f
#define UCTAS 128          // k_u CTAs; each owns 16 consecutive i

// Scratch (device globals: allocation-free rule)
__device__ __half g_u[(size_t)B_ * N_ * JD_];        // 134 MB u[b][i][jd] fp16
__device__ float  g_part1[(size_t)UCTAS * B_ * JD_]; // s1 partials per k_u CTA
__device__ float  g_s[2][B_ * JD_];                  // s2, s3 accumulators
__device__ float  g_v[2][B_ * JD_];                  // v1, (v1+v2)

__device__ __forceinline__ uint32_t packh2(float a, float b) {
    __half2 h = __floats2half2_rn(a, b);
    return *(uint32_t*)&h;
}
__device__ __forceinline__ void mma16816(float& d0, float& d1, float& d2, float& d3,
        uint32_t a0, uint32_t a1, uint32_t a2, uint32_t a3,
        uint32_t b0, uint32_t b1) {
    asm volatile(
        "mma.sync.aligned.m16n8k16.row.col.f32.f16.f16.f32 "
        "{%0,%1,%2,%3}, {%4,%5,%6,%7}, {%8,%9}, {%10,%11,%12,%13};\n"
        : "=f"(d0), "=f"(d1), "=f"(d2), "=f"(d3)
        : "r"(a0), "r"(a1), "r"(a2), "r"(a3), "r"(b0), "r"(b1),
          "f"(0.f), "f"(0.f), "f"(0.f), "f"(0.f));
}

// ---------------------------------------------------------------------------
// Zero s accumulators (graph replays need re-zeroing)
// ---------------------------------------------------------------------------
__global__ void k_zero() {
    int idx = blockIdx.x * blockDim.x + threadIdx.x;   // 64*1024 = 65536 = 2*64*512
    ((float*)g_s)[idx] = 0.0f;
}

// ---------------------------------------------------------------------------
// k_u: tensor-core einsum + fused pass 1.
// Per i: C[b=64, jd=512] = X_i[64 x 16(e)] * W_i^T[16(e) x 512(jd)], m16n8k16.
// CTA = 16 consecutive i's, 512 threads = 16 warps.
// Warp w: M-tile mt = w&3 (16 b's), N-tiles q=0..15 at jd = (w>>2)*128 + q*8.
// Per mma: write u fp16; accumulate s1 (uniform c) in registers across 16 i's.
// ---------------------------------------------------------------------------
__global__ __launch_bounds__(512, 1) void k_u(const float* __restrict__ x,
                                              const float* __restrict__ w) {
    const int cta  = blockIdx.x;
    const int t    = threadIdx.x;
    const int wid  = t >> 5;
    const int lane = t & 31;
    const int g    = lane >> 2;     // groupID
    const int tg   = lane & 3;      // threadID_in_group
    const int mt   = wid & 3;
    const int jd0  = (wid >> 2) * 128;
    const int bA   = mt * 16 + g;   // A rows bA, bA+8
    const int jdC  = jd0 + 2 * tg;  // C col base (per q add q*8)
    const int jdB  = jd0 + g;       // B col base (per q add q*8)

    float acc[16][4];
#pragma unroll
    for (int q = 0; q < 16; q++)
#pragma unroll
        for (int r = 0; r < 4; r++) acc[q][r] = 0.f;

    for (int k = 0; k < 16; k++) {
        const int i = cta * 16 + k;

        // A fragment from x[b][i][e] (fp32 -> fp16)
        const float* xp0 = x + ((size_t)bA * N_ + i) * 16 + 2 * tg;
        const float* xp1 = x + ((size_t)(bA + 8) * N_ + i) * 16 + 2 * tg;
        float2 f0 = *(const float2*)xp0;        // (bA,   e)
        float2 f1 = *(const float2*)xp1;        // (bA+8, e)
        float2 f2 = *(const float2*)(xp0 + 8);  // (bA,   e+8)
        float2 f3 = *(const float2*)(xp1 + 8);  // (bA+8, e+8)
        uint32_t A0 = packh2(f0.x, f0.y);
        uint32_t A1 = packh2(f1.x, f1.y);
        uint32_t A2 = packh2(f2.x, f2.y);
        uint32_t A3 = packh2(f3.x, f3.y);

        __half* ub = g_u + ((size_t)bA * N_ + i) * JD_;   // row bA of u (bA+8 at +8*N_*JD_)

#pragma unroll
        for (int q = 0; q < 16; q++) {
            // B fragment from w[i][jd][e] (fp32 -> fp16): col jdB+q*8, rows e
            const float* wp = w + ((size_t)i * JD_ + jdB + q * 8) * 16 + 2 * tg;
            float2 w0 = *(const float2*)wp;        // (e,   jd)
            float2 w1 = *(const float2*)(wp + 8);  // (e+8, jd)
            uint32_t Bb0 = packh2(w0.x, w0.y);
            uint32_t Bb1 = packh2(w1.x, w1.y);

            float d0, d1, d2, d3;
            mma16816(d0, d1, d2, d3, A0, A1, A2, A3, Bb0, Bb1);

            acc[q][0] += d0; acc[q][1] += d1;
            acc[q][2] += d2; acc[q][3] += d3;

            const int jc = jdC + q * 8;
            *(uint32_t*)(ub + jc)                        = packh2(d0, d1);
            *(uint32_t*)(ub + jc + (size_t)8 * N_ * JD_) = packh2(d2, d3);
        }
    }

    // write s1 partials: g_part1[cta][b*512 + jd]
    float* pb = g_part1 + (size_t)cta * (B_ * JD_) + (size_t)bA * JD_;
#pragma unroll
    for (int q = 0; q < 16; q++) {
        const int jc = jdC + q * 8;
        *(float2*)(pb + jc)           = make_float2(acc[q][0], acc[q][1]);
        *(float2*)(pb + jc + 8 * JD_) = make_float2(acc[q][2], acc[q][3]);
    }
}

// ---------------------------------------------------------------------------
// Routing sweep reading fp16 u: per (b,i): logit[j] = u.v, softmax over j,
// s[sIdx][b,j,d] += c[j]*u[j,d]. Grid (16, 64), 256 thr = 8 warps x 16 i, lane=j.
// ---------------------------------------------------------------------------
__global__ __launch_bounds__(256) void k_pass(int vIdx, int sIdx) {
    const int b    = blockIdx.y;
    const int ic   = blockIdx.x;
    const int t    = threadIdx.x;
    const int warp = t >> 5;
    const int j    = t & 31;

    __shared__ float vs[JD_];
    __shared__ float ss[8][JD_];

    for (int idx = t; idx < JD_; idx += 256)
        vs[idx] = g_v[vIdx][b * JD_ + idx];
    __syncthreads();

    float vj[16];
#pragma unroll
    for (int d = 0; d < 16; d++) vj[d] = vs[j * 16 + d];

    float acc[16];
#pragma unroll
    for (int d = 0; d < 16; d++) acc[d] = 0.f;

    const int ibase = ic * 128 + warp * 16;
    for (int k = 0; k < 16; k++) {
        const int i = ibase + k;
        const uint4* up = (const uint4*)(g_u + ((size_t)b * N_ + i) * JD_ + j * 16);
        uint4 p0 = up[0], p1 = up[1];

        float u[16];
        {
            const __half2* h0 = (const __half2*)&p0;
            const __half2* h1 = (const __half2*)&p1;
#pragma unroll
            for (int q = 0; q < 4; q++) {
                float2 a = __half22float2(h0[q]);
                u[q*2+0] = a.x; u[q*2+1] = a.y;
                float2 c2 = __half22float2(h1[q]);
                u[8+q*2+0] = c2.x; u[8+q*2+1] = c2.y;
            }
        }

        float bl = 0.f;
#pragma unroll
        for (int d = 0; d < 16; d++) bl += u[d] * vj[d];
        float m = bl;
#pragma unroll
        for (int o = 16; o > 0; o >>= 1)
            m = fmaxf(m, __shfl_xor_sync(0xffffffffu, m, o));
        float ex = __expf(bl - m);
        float sum = ex;
#pragma unroll
        for (int o = 16; o > 0; o >>= 1)
            sum += __shfl_xor_sync(0xffffffffu, sum, o);
        float c = ex / sum;

#pragma unroll
        for (int d = 0; d < 16; d++) acc[d] += c * u[d];
    }

#pragma unroll
    for (int d = 0; d < 16; d++) ss[warp][d * 32 + j] = acc[d];
    __syncthreads();

    for (int idx = t; idx < JD_; idx += 256) {
        int d = idx >> 5, jj = idx & 31;
        float r = 0.f;
#pragma unroll
        for (int wi = 0; wi < 8; wi++) r += ss[wi][idx];
        atomicAdd(&g_s[sIdx][b * JD_ + jj * 16 + d], r);
    }
}

// ---------------------------------------------------------------------------
// v1 = squash_J( (1/32) * reduce(g_part1) )
// ---------------------------------------------------------------------------
__global__ void k_squash_s1() {
    const int b = blockIdx.x;
    const int t = threadIdx.x;     // t = j*16 + d
    float s = 0.f;
#pragma unroll 4
    for (int c = 0; c < UCTAS; c++)
        s += g_part1[(size_t)c * (B_ * JD_) + b * JD_ + t];
    s *= (1.0f / 32.0f);

    __shared__ float sq[16];
    if (t < 16) sq[t] = 0.f;
    __syncthreads();
    atomicAdd(&sq[t & 15], s * s);
    __syncthreads();
    float q = sq[t & 15];
    g_v[0][b * JD_ + t] = s * (q / (1.f + q)) * rsqrtf(q + EPS_);
}

// ---------------------------------------------------------------------------
// vsum = squash_J(s2) + v1
// ---------------------------------------------------------------------------
__global__ void k_squash_j() {
    const int b = blockIdx.x;
    const int t = threadIdx.x;
    float s = g_s[0][b * JD_ + t];
    __shared__ float sq[16];
    if (t < 16) sq[t] = 0.f;
    __syncthreads();
    atomicAdd(&sq[t & 15], s * s);
    __syncthreads();
    float q = sq[t & 15];
    float v = s * (q / (1.f + q)) * rsqrtf(q + EPS_);
    g_v[1][b * JD_ + t] = v + g_v[0][b * JD_ + t];
}

// ---------------------------------------------------------------------------
// out = squash_D(s3)
// ---------------------------------------------------------------------------
__global__ void k_final(float* __restrict__ out) {
    const int b = blockIdx.x;
    const int t = threadIdx.x;     // t = j*16 + d
    float s = g_s[1][b * JD_ + t];
    float q = s * s;
#pragma unroll
    for (int o = 1; o < 16; o <<= 1)
        q += __shfl_xor_sync(0xffffffffu, q, o);
    float v = s * (q / (1.f + q)) * rsqrtf(q + EPS_);
    out[b * JD_ + t] = v;
}

// ---------------------------------------------------------------------------
extern "C" void kernel_launch(void* const* d_in, const int* in_sizes, int n_in,
                              void* d_out, int out_size) {
    const float* x = (const float*)d_in[0];
    const float* w = (const float*)d_in[1];
    if (in_sizes[0] != B_ * N_ * 16) {       // defensive input-order check
        x = (const float*)d_in[1];
        w = (const float*)d_in[0];
    }

    k_zero<<<64, 1024>>>();
    k_u<<<UCTAS, 512>>>(x, w);               // u (fp16) + fused pass 1 partials
    k_squash_s1<<<B_, JD_>>>();              // v1
    dim3 pg(16, B_);
    k_pass<<<pg, 256>>>(0, 0);               // iter 2: c=softmax(u.v1) -> s2
    k_squash_j<<<B_, JD_>>>();               // vsum = squash_J(s2) + v1
    k_pass<<<pg, 256>>>(1, 1);               // final: c=softmax(u.vsum) -> s3
    k_final<<<B_, JD_>>>((float*)d_out);     // out = squash_D(s3)
}